// round 2
// baseline (speedup 1.0000x reference)
#include <cuda_runtime.h>
#include <cuda_bf16.h>
#include <math.h>

#define N_NODES 100000
#define N_EDGES 1600000
#define NFEAT 256
#define NHID 128
#define NCLASS 64

// ---------------- scratch (device globals; no allocation) ----------------
__device__ float g_h1[3u * N_NODES * NHID];    // feat @ W1      (153.6 MB)
__device__ float g_agg1[3u * N_NODES * NHID];  // relu(spmm+b1)  (153.6 MB)
__device__ float g_h2[3u * N_NODES * NCLASS];  // agg1 @ W2      (76.8 MB)
__device__ int g_rowptr[N_NODES + 1];

// ---------------- row_ptr from sorted edge_dst ----------------
__global__ void build_rowptr_kernel(const int* __restrict__ dst) {
    int v = blockIdx.x * blockDim.x + threadIdx.x;
    if (v > N_NODES) return;
    int lo = 0, hi = N_EDGES;
    while (lo < hi) {
        int mid = (lo + hi) >> 1;
        if (dst[mid] < v) lo = mid + 1; else hi = mid;
    }
    g_rowptr[v] = lo;
}

// ---------------- tiled fp32 GEMM: C[M,N] = A[M,K] @ B[K,N] ----------------
template <int BM, int BN, int BK, int TM, int TN>
__global__ __launch_bounds__((BM / TM) * (BN / TN))
void sgemm_kernel(const float* __restrict__ A, const float* __restrict__ B,
                  float* __restrict__ C, int M, int N, int K) {
    constexpr int THREADS = (BM / TM) * (BN / TN);
    __shared__ float As[BK][BM];
    __shared__ float Bs[BK][BN];

    const int tid = threadIdx.x;
    const int tx = tid % (BN / TN);
    const int ty = tid / (BN / TN);
    const int row0 = blockIdx.x * BM;
    const int col0 = blockIdx.y * BN;

    float acc[TM][TN];
#pragma unroll
    for (int i = 0; i < TM; ++i)
#pragma unroll
        for (int j = 0; j < TN; ++j) acc[i][j] = 0.f;

    constexpr int A_F4 = BM * BK / 4;
    constexpr int A_PER = A_F4 / THREADS;
    constexpr int B_F4 = BK * BN / 4;
    constexpr int B_PER = (B_F4 + THREADS - 1) / THREADS;

    for (int k0 = 0; k0 < K; k0 += BK) {
        // A tile -> As[k][m] (transposed store)
#pragma unroll
        for (int i = 0; i < A_PER; ++i) {
            int idx = tid + i * THREADS;
            int m = idx / (BK / 4);
            int kk = (idx % (BK / 4)) * 4;
            float4 v = make_float4(0.f, 0.f, 0.f, 0.f);
            int gr = row0 + m;
            if (gr < M)
                v = *reinterpret_cast<const float4*>(A + (size_t)gr * K + k0 + kk);
            As[kk + 0][m] = v.x;
            As[kk + 1][m] = v.y;
            As[kk + 2][m] = v.z;
            As[kk + 3][m] = v.w;
        }
        // B tile -> Bs[k][n]
#pragma unroll
        for (int i = 0; i < B_PER; ++i) {
            int idx = tid + i * THREADS;
            if (idx < B_F4) {
                int kk = idx / (BN / 4);
                int n = (idx % (BN / 4)) * 4;
                float4 v = *reinterpret_cast<const float4*>(
                    B + (size_t)(k0 + kk) * N + col0 + n);
                *reinterpret_cast<float4*>(&Bs[kk][n]) = v;
            }
        }
        __syncthreads();

#pragma unroll
        for (int k = 0; k < BK; ++k) {
            float ra[TM], rb[TN];
#pragma unroll
            for (int i = 0; i < TM; ++i) ra[i] = As[k][ty * TM + i];
#pragma unroll
            for (int j = 0; j < TN; ++j) rb[j] = Bs[k][tx * TN + j];
#pragma unroll
            for (int i = 0; i < TM; ++i)
#pragma unroll
                for (int j = 0; j < TN; ++j) acc[i][j] += ra[i] * rb[j];
        }
        __syncthreads();
    }

#pragma unroll
    for (int i = 0; i < TM; ++i) {
        int gr = row0 + ty * TM + i;
        if (gr >= M) continue;
#pragma unroll
        for (int j = 0; j < TN; j += 4) {
            float4 v = make_float4(acc[i][j], acc[i][j + 1], acc[i][j + 2], acc[i][j + 3]);
            *reinterpret_cast<float4*>(C + (size_t)gr * N + col0 + tx * TN + j) = v;
        }
    }
}

// ---------------- SpMM layer 1: agg = relu(segsum(w * h1[src]) + b1) ----------------
// grid (N_NODES, 3), 32 threads; each thread owns 4 contiguous dims (float4).
__global__ __launch_bounds__(32)
void spmm1_bias_relu_kernel(const float4* __restrict__ src_h, // g_h1 as float4
                            const int* __restrict__ esrc,
                            const float* __restrict__ ew,
                            const float4* __restrict__ b1,
                            float4* __restrict__ outp) { // g_agg1 as float4
    const int v = blockIdx.x;
    const int b = blockIdx.y;
    const int d = threadIdx.x;               // 0..31, covers 4 dims each (NHID/4 = 32)
    const float4* Hb = src_h + (size_t)b * N_NODES * (NHID / 4);
    const int e0 = g_rowptr[v];
    const int e1 = g_rowptr[v + 1];
    float4 acc = make_float4(0.f, 0.f, 0.f, 0.f);
    for (int e = e0; e < e1; ++e) {
        int s = __ldg(&esrc[e]);
        float w = __ldg(&ew[e]);
        float4 h = __ldg(&Hb[(size_t)s * (NHID / 4) + d]);
        acc.x += w * h.x; acc.y += w * h.y; acc.z += w * h.z; acc.w += w * h.w;
    }
    float4 bb = __ldg(&b1[d]);
    float4 r;
    r.x = fmaxf(acc.x + bb.x, 0.f);
    r.y = fmaxf(acc.y + bb.y, 0.f);
    r.z = fmaxf(acc.z + bb.z, 0.f);
    r.w = fmaxf(acc.w + bb.w, 0.f);
    outp[((size_t)b * N_NODES + v) * (NHID / 4) + d] = r;
}

// ---------------- SpMM layer 2 + bias + log_softmax, writes o_b directly ----------------
// grid (N_NODES, 3), 16 threads? -> keep a full warp of 32 but only 16 lanes work.
// Use 32 threads: lanes 0..15 each own 4 dims (NCLASS/4 = 16); lanes 16..31 idle in
// the gather but participate in shuffles (their values are neutral).
__global__ __launch_bounds__(32)
void spmm2_lsm_kernel(const float4* __restrict__ src_h, // g_h2 as float4
                      const int* __restrict__ esrc,
                      const float* __restrict__ ew,
                      const float4* __restrict__ b2,
                      float* __restrict__ out) { // d_out base
    const int v = blockIdx.x;
    const int b = blockIdx.y;
    const int lane = threadIdx.x;            // 0..31
    const bool active = lane < (NCLASS / 4); // 16 active lanes
    const float4* Hb = src_h + (size_t)b * N_NODES * (NCLASS / 4);
    const int e0 = g_rowptr[v];
    const int e1 = g_rowptr[v + 1];
    float4 acc = make_float4(0.f, 0.f, 0.f, 0.f);
    if (active) {
        for (int e = e0; e < e1; ++e) {
            int s = __ldg(&esrc[e]);
            float w = __ldg(&ew[e]);
            float4 h = __ldg(&Hb[(size_t)s * (NCLASS / 4) + lane]);
            acc.x += w * h.x; acc.y += w * h.y; acc.z += w * h.z; acc.w += w * h.w;
        }
        float4 bb = __ldg(&b2[lane]);
        acc.x += bb.x; acc.y += bb.y; acc.z += bb.z; acc.w += bb.w;
    }

    // warp log-softmax over 64 values held as 4/lane in lanes 0..15
    float m = active ? fmaxf(fmaxf(acc.x, acc.y), fmaxf(acc.z, acc.w)) : -INFINITY;
#pragma unroll
    for (int o = 16; o; o >>= 1) m = fmaxf(m, __shfl_xor_sync(0xffffffffu, m, o));

    float s = 0.f;
    if (active)
        s = expf(acc.x - m) + expf(acc.y - m) + expf(acc.z - m) + expf(acc.w - m);
#pragma unroll
    for (int o = 16; o; o >>= 1) s += __shfl_xor_sync(0xffffffffu, s, o);

    float lse = m + logf(s);
    if (active) {
        float4 r;
        r.x = acc.x - lse; r.y = acc.y - lse; r.z = acc.z - lse; r.w = acc.w - lse;
        float4* ob = reinterpret_cast<float4*>(
            out + (size_t)b * N_NODES * NCLASS + (size_t)v * NCLASS);
        ob[lane] = r;
    }
}

// ---------------- final mean of 3 branches ----------------
__global__ void mean3_kernel(const float4* __restrict__ out_base, float4* __restrict__ fin) {
    size_t i = (size_t)blockIdx.x * blockDim.x + threadIdx.x;
    const size_t total = (size_t)N_NODES * NCLASS / 4;
    if (i >= total) return;
    float4 a = out_base[i];
    float4 bb = out_base[total + i];
    float4 c = out_base[2 * total + i];
    float4 r;
    r.x = (a.x + bb.x + c.x) * (1.0f / 3.0f);
    r.y = (a.y + bb.y + c.y) * (1.0f / 3.0f);
    r.z = (a.z + bb.z + c.z) * (1.0f / 3.0f);
    r.w = (a.w + bb.w + c.w) * (1.0f / 3.0f);
    fin[i] = r;
}

// ---------------- launch ----------------
extern "C" void kernel_launch(void* const* d_in, const int* in_sizes, int n_in,
                              void* d_out, int out_size) {
    const float* x   = (const float*)d_in[0];
    const float* dr1 = (const float*)d_in[1];
    const float* dr2 = (const float*)d_in[2];
    const int*   esrc = (const int*)d_in[3];
    const int*   edst = (const int*)d_in[4];
    const float* ew  = (const float*)d_in[5];
    const float* W1  = (const float*)d_in[6];
    const float* b1  = (const float*)d_in[7];
    const float* W2  = (const float*)d_in[8];
    const float* b2  = (const float*)d_in[9];
    float* out = (float*)d_out;

    float *h1, *agg1, *h2;
    cudaGetSymbolAddress((void**)&h1, g_h1);
    cudaGetSymbolAddress((void**)&agg1, g_agg1);
    cudaGetSymbolAddress((void**)&h2, g_h2);

    // 1) row pointers from sorted edge_dst
    build_rowptr_kernel<<<(N_NODES + 1 + 255) / 256, 256>>>(edst);

    // 2) GEMM1 per branch: h1[b] = feat_b @ W1   [100000,256]@[256,128]
    {
        dim3 grid((N_NODES + 127) / 128, 1);
        sgemm_kernel<128, 128, 16, 8, 8><<<grid, 256>>>(
            x, W1, h1 + 0 * (size_t)N_NODES * NHID, N_NODES, NHID, NFEAT);
        sgemm_kernel<128, 128, 16, 8, 8><<<grid, 256>>>(
            dr1, W1, h1 + 1 * (size_t)N_NODES * NHID, N_NODES, NHID, NFEAT);
        sgemm_kernel<128, 128, 16, 8, 8><<<grid, 256>>>(
            dr2, W1, h1 + 2 * (size_t)N_NODES * NHID, N_NODES, NHID, NFEAT);
    }

    // 3) SpMM1 + bias + relu
    {
        dim3 grid(N_NODES, 3);
        spmm1_bias_relu_kernel<<<grid, 32>>>(
            (const float4*)h1, esrc, ew, (const float4*)b1, (float4*)agg1);
    }

    // 4) GEMM2: h2 = agg1 @ W2   [300000,128]@[128,64]
    {
        dim3 grid((3 * N_NODES + 127) / 128, 1);
        sgemm_kernel<128, 64, 16, 8, 4><<<grid, 256>>>(
            agg1, W2, h2, 3 * N_NODES, NCLASS, NHID);
    }

    // 5) SpMM2 + bias + log_softmax -> o1,o2,o3 written straight to d_out
    {
        dim3 grid(N_NODES, 3);
        spmm2_lsm_kernel<<<grid, 32>>>(
            (const float4*)h2, esrc, ew, (const float4*)b2, out);
    }

    // 6) final = mean(o1,o2,o3) -> 4th section of d_out
    {
        const size_t total = (size_t)N_NODES * NCLASS;
        mean3_kernel<<<(unsigned)((total / 4 + 255) / 256), 256>>>(
            (const float4*)out, (float4*)(out + 3 * total));
    }
}

// round 7
// speedup vs baseline: 1.2720x; 1.2720x over previous
#include <cuda_runtime.h>
#include <cuda_bf16.h>
#include <mma.h>
#include <math.h>
#include <stdint.h>

using namespace nvcuda;

#define N_NODES 100000
#define N_EDGES 1600000
#define NFEAT 256
#define NHID 128
#define NCLASS 64
#define M_PAD 100096          // 782 * 128, padded row count per branch

// ---------------- scratch (device globals; no allocation) ----------------
// Pad rows [N_NODES, M_PAD) of g_agg1 are never written by any kernel (zero-init
// globals persist), so GEMM2's unguarded reads of them are deterministic zeros.
__device__ float g_h1[3u * M_PAD * NHID];
__device__ float g_agg1[3u * M_PAD * NHID];
__device__ float g_h2[3u * M_PAD * NCLASS];
__device__ int g_rowptr[N_NODES + 1];
// W split to bf16 hi/lo, kept in original [K, N] row-major layout
__device__ __nv_bfloat16 g_W1_hi[NFEAT * NHID];
__device__ __nv_bfloat16 g_W1_lo[NFEAT * NHID];
__device__ __nv_bfloat16 g_W2_hi[NHID * NCLASS];
__device__ __nv_bfloat16 g_W2_lo[NHID * NCLASS];

__device__ __forceinline__ void split2(float v, __nv_bfloat16& h, __nv_bfloat16& l) {
    h = __float2bfloat16(v);
    l = __float2bfloat16(v - __bfloat162float(h));
}

// ---------------- row_ptr from sorted edge_dst ----------------
__global__ void build_rowptr_kernel(const int* __restrict__ dst) {
    int v = blockIdx.x * blockDim.x + threadIdx.x;
    if (v > N_NODES) return;
    int lo = 0, hi = N_EDGES;
    while (lo < hi) {
        int mid = (lo + hi) >> 1;
        if (dst[mid] < v) lo = mid + 1; else hi = mid;
    }
    g_rowptr[v] = lo;
}

// ---------------- W bf16 split (tiny, once per launch) ----------------
__global__ void prep_w_kernel(const float* __restrict__ W1, const float* __restrict__ W2) {
    int i = blockIdx.x * blockDim.x + threadIdx.x;
    if (i < NFEAT * NHID) {
        __nv_bfloat16 h, l;
        split2(W1[i], h, l);
        g_W1_hi[i] = h;
        g_W1_lo[i] = l;
    }
    if (i < NHID * NCLASS) {
        __nv_bfloat16 h, l;
        split2(W2[i], h, l);
        g_W2_hi[i] = h;
        g_W2_lo[i] = l;
    }
}

// ================= split-bf16 GEMM via wmma (HMMA tensor cores) =================
// C[M, N_DIM] = A[M, K_DIM] @ B[K_DIM, N_DIM]
// B given pre-split as bf16 hi/lo ([K,N] row-major). A split in the tile loader.
// acc += Ahi@Bhi + Ahi@Blo + Alo@Bhi   (fp32 accumulators)
// Block tile 128 x N_DIM, BK=32, 256 threads = 8 warps in a 4x2 grid,
// warp tile 32 x (N_DIM/2).
template <int N_DIM, int K_DIM>
__global__ __launch_bounds__(256)
void wmma_gemm_kernel(const float* __restrict__ A,
                      const __nv_bfloat16* __restrict__ Bhi,
                      const __nv_bfloat16* __restrict__ Blo,
                      float* __restrict__ C, int M_A) {
    constexpr int BM = 128, BK = 32;
    constexpr int NCHUNK = K_DIM / BK;
    constexpr int LDA = BK + 8;          // bf16 elements
    constexpr int LDB = N_DIM + 8;
    constexpr int NF = N_DIM / 32;       // n-frags per warp
    constexpr int MF = 2;                // m-frags per warp (32 rows)

    __shared__ __nv_bfloat16 As_hi[BM * LDA];
    __shared__ __nv_bfloat16 As_lo[BM * LDA];
    __shared__ __nv_bfloat16 Bs_hi[BK * LDB];
    __shared__ __nv_bfloat16 Bs_lo[BK * LDB];

    const int tid = threadIdx.x;
    const int wid = tid >> 5;
    const int warp_m = wid & 3;          // 0..3
    const int warp_n = wid >> 2;         // 0..1
    const int row0 = blockIdx.x * BM;

    wmma::fragment<wmma::accumulator, 16, 16, 16, float> acc[MF][NF];
#pragma unroll
    for (int i = 0; i < MF; ++i)
#pragma unroll
        for (int j = 0; j < NF; ++j) wmma::fill_fragment(acc[i][j], 0.f);

    for (int kc = 0; kc < NCHUNK; ++kc) {
        const int k0 = kc * BK;

        // ---- A tile [128 x 32] fp32 -> split bf16 hi/lo in smem ----
        // 1024 float4 total; 256 threads -> 4 each
#pragma unroll
        for (int i = 0; i < 4; ++i) {
            int j = tid + i * 256;
            int m = j >> 3;              // 8 float4 per row
            int c = (j & 7) * 4;
            float4 v = make_float4(0.f, 0.f, 0.f, 0.f);
            int gm = row0 + m;
            if (gm < M_A)
                v = *reinterpret_cast<const float4*>(A + (size_t)gm * K_DIM + k0 + c);
            __nv_bfloat16 h0, l0, h1, l1, h2, l2, h3, l3;
            split2(v.x, h0, l0); split2(v.y, h1, l1);
            split2(v.z, h2, l2); split2(v.w, h3, l3);
            uint32_t hh0 = (uint32_t)__bfloat16_as_ushort(h0) |
                           ((uint32_t)__bfloat16_as_ushort(h1) << 16);
            uint32_t hh1 = (uint32_t)__bfloat16_as_ushort(h2) |
                           ((uint32_t)__bfloat16_as_ushort(h3) << 16);
            uint32_t ll0 = (uint32_t)__bfloat16_as_ushort(l0) |
                           ((uint32_t)__bfloat16_as_ushort(l1) << 16);
            uint32_t ll1 = (uint32_t)__bfloat16_as_ushort(l2) |
                           ((uint32_t)__bfloat16_as_ushort(l3) << 16);
            *reinterpret_cast<uint2*>(&As_hi[m * LDA + c]) = make_uint2(hh0, hh1);
            *reinterpret_cast<uint2*>(&As_lo[m * LDA + c]) = make_uint2(ll0, ll1);
        }

        // ---- B tile [32 x N_DIM] bf16 hi/lo -> smem ----
        constexpr int BU4 = BK * N_DIM / 8;   // uint4 (8 bf16) count
#pragma unroll
        for (int i = 0; i < (BU4 + 255) / 256; ++i) {
            int j = tid + i * 256;
            if (j < BU4) {
                int r = j / (N_DIM / 8);
                int c8 = j % (N_DIM / 8);
                uint4 vh = *reinterpret_cast<const uint4*>(
                    Bhi + (size_t)(k0 + r) * N_DIM + c8 * 8);
                uint4 vl = *reinterpret_cast<const uint4*>(
                    Blo + (size_t)(k0 + r) * N_DIM + c8 * 8);
                *reinterpret_cast<uint4*>(&Bs_hi[r * LDB + c8 * 8]) = vh;
                *reinterpret_cast<uint4*>(&Bs_lo[r * LDB + c8 * 8]) = vl;
            }
        }
        __syncthreads();

        // ---- 2 k-steps of 16, 3-term split accumulation ----
#pragma unroll
        for (int kk = 0; kk < 2; ++kk) {
            wmma::fragment<wmma::matrix_a, 16, 16, 16, __nv_bfloat16, wmma::row_major> ah[MF], al[MF];
            wmma::fragment<wmma::matrix_b, 16, 16, 16, __nv_bfloat16, wmma::row_major> bh[NF], bl[NF];
#pragma unroll
            for (int i = 0; i < MF; ++i) {
                const int r = (warp_m * 32 + i * 16) * LDA + kk * 16;
                wmma::load_matrix_sync(ah[i], &As_hi[r], LDA);
                wmma::load_matrix_sync(al[i], &As_lo[r], LDA);
            }
#pragma unroll
            for (int j = 0; j < NF; ++j) {
                const int cidx = kk * 16 * LDB + warp_n * (N_DIM / 2) + j * 16;
                wmma::load_matrix_sync(bh[j], &Bs_hi[cidx], LDB);
                wmma::load_matrix_sync(bl[j], &Bs_lo[cidx], LDB);
            }
#pragma unroll
            for (int i = 0; i < MF; ++i)
#pragma unroll
                for (int j = 0; j < NF; ++j) {
                    wmma::mma_sync(acc[i][j], ah[i], bh[j], acc[i][j]);
                    wmma::mma_sync(acc[i][j], ah[i], bl[j], acc[i][j]);
                    wmma::mma_sync(acc[i][j], al[i], bh[j], acc[i][j]);
                }
        }
        __syncthreads();
    }

    // ---- epilogue: unguarded stores (C rows padded to multiple of 128) ----
#pragma unroll
    for (int i = 0; i < MF; ++i) {
        int gm = row0 + warp_m * 32 + i * 16;
#pragma unroll
        for (int j = 0; j < NF; ++j) {
            wmma::store_matrix_sync(C + (size_t)gm * N_DIM + warp_n * (N_DIM / 2) + j * 16,
                                    acc[i][j], N_DIM, wmma::mem_row_major);
        }
    }
}

// ---------------- SpMM layer 1: agg = relu(segsum(w * h1[src]) + b1) ----------------
__global__ __launch_bounds__(32)
void spmm1_bias_relu_kernel(const float4* __restrict__ src_h,
                            const int* __restrict__ esrc,
                            const float* __restrict__ ew,
                            const float4* __restrict__ b1,
                            float4* __restrict__ outp) {
    const int v = blockIdx.x;
    const int b = blockIdx.y;
    const int d = threadIdx.x;
    const float4* Hb = src_h + (size_t)b * M_PAD * (NHID / 4);
    const int e0 = g_rowptr[v];
    const int e1 = g_rowptr[v + 1];
    float4 acc = make_float4(0.f, 0.f, 0.f, 0.f);
    for (int e = e0; e < e1; ++e) {
        int s = __ldg(&esrc[e]);
        float w = __ldg(&ew[e]);
        float4 h = __ldg(&Hb[(size_t)s * (NHID / 4) + d]);
        acc.x += w * h.x; acc.y += w * h.y; acc.z += w * h.z; acc.w += w * h.w;
    }
    float4 bb = __ldg(&b1[d]);
    float4 r;
    r.x = fmaxf(acc.x + bb.x, 0.f);
    r.y = fmaxf(acc.y + bb.y, 0.f);
    r.z = fmaxf(acc.z + bb.z, 0.f);
    r.w = fmaxf(acc.w + bb.w, 0.f);
    outp[((size_t)b * M_PAD + v) * (NHID / 4) + d] = r;
}

// ---------------- SpMM layer 2 + bias + log_softmax ----------------
__global__ __launch_bounds__(32)
void spmm2_lsm_kernel(const float4* __restrict__ src_h,
                      const int* __restrict__ esrc,
                      const float* __restrict__ ew,
                      const float4* __restrict__ b2,
                      float* __restrict__ out) {
    const int v = blockIdx.x;
    const int b = blockIdx.y;
    const int lane = threadIdx.x;
    const bool active = lane < (NCLASS / 4);
    const float4* Hb = src_h + (size_t)b * M_PAD * (NCLASS / 4);
    const int e0 = g_rowptr[v];
    const int e1 = g_rowptr[v + 1];
    float4 acc = make_float4(0.f, 0.f, 0.f, 0.f);
    if (active) {
        for (int e = e0; e < e1; ++e) {
            int s = __ldg(&esrc[e]);
            float w = __ldg(&ew[e]);
            float4 h = __ldg(&Hb[(size_t)s * (NCLASS / 4) + lane]);
            acc.x += w * h.x; acc.y += w * h.y; acc.z += w * h.z; acc.w += w * h.w;
        }
        float4 bb = __ldg(&b2[lane]);
        acc.x += bb.x; acc.y += bb.y; acc.z += bb.z; acc.w += bb.w;
    }

    float m = active ? fmaxf(fmaxf(acc.x, acc.y), fmaxf(acc.z, acc.w)) : -INFINITY;
#pragma unroll
    for (int o = 16; o; o >>= 1) m = fmaxf(m, __shfl_xor_sync(0xffffffffu, m, o));

    float s = 0.f;
    if (active)
        s = expf(acc.x - m) + expf(acc.y - m) + expf(acc.z - m) + expf(acc.w - m);
#pragma unroll
    for (int o = 16; o; o >>= 1) s += __shfl_xor_sync(0xffffffffu, s, o);

    float lse = m + logf(s);
    if (active) {
        float4 r;
        r.x = acc.x - lse; r.y = acc.y - lse; r.z = acc.z - lse; r.w = acc.w - lse;
        float4* ob = reinterpret_cast<float4*>(
            out + (size_t)b * N_NODES * NCLASS + (size_t)v * NCLASS);
        ob[lane] = r;
    }
}

// ---------------- final mean of 3 branches ----------------
__global__ void mean3_kernel(const float4* __restrict__ out_base, float4* __restrict__ fin) {
    size_t i = (size_t)blockIdx.x * blockDim.x + threadIdx.x;
    const size_t total = (size_t)N_NODES * NCLASS / 4;
    if (i >= total) return;
    float4 a = out_base[i];
    float4 bb = out_base[total + i];
    float4 c = out_base[2 * total + i];
    float4 r;
    r.x = (a.x + bb.x + c.x) * (1.0f / 3.0f);
    r.y = (a.y + bb.y + c.y) * (1.0f / 3.0f);
    r.z = (a.z + bb.z + c.z) * (1.0f / 3.0f);
    r.w = (a.w + bb.w + c.w) * (1.0f / 3.0f);
    fin[i] = r;
}

// ---------------- launch ----------------
extern "C" void kernel_launch(void* const* d_in, const int* in_sizes, int n_in,
                              void* d_out, int out_size) {
    const float* x   = (const float*)d_in[0];
    const float* dr1 = (const float*)d_in[1];
    const float* dr2 = (const float*)d_in[2];
    const int*   esrc = (const int*)d_in[3];
    const int*   edst = (const int*)d_in[4];
    const float* ew  = (const float*)d_in[5];
    const float* W1  = (const float*)d_in[6];
    const float* b1  = (const float*)d_in[7];
    const float* W2  = (const float*)d_in[8];
    const float* b2  = (const float*)d_in[9];
    float* out = (float*)d_out;

    float *h1, *agg1, *h2;
    cudaGetSymbolAddress((void**)&h1, g_h1);
    cudaGetSymbolAddress((void**)&agg1, g_agg1);
    cudaGetSymbolAddress((void**)&h2, g_h2);
    __nv_bfloat16 *w1h, *w1l, *w2h, *w2l;
    cudaGetSymbolAddress((void**)&w1h, g_W1_hi);
    cudaGetSymbolAddress((void**)&w1l, g_W1_lo);
    cudaGetSymbolAddress((void**)&w2h, g_W2_hi);
    cudaGetSymbolAddress((void**)&w2l, g_W2_lo);

    // 0) prep: row pointers + W split
    build_rowptr_kernel<<<(N_NODES + 1 + 255) / 256, 256>>>(edst);
    prep_w_kernel<<<(NFEAT * NHID + 255) / 256, 256>>>(W1, W2);

    // 1) GEMM1 per branch: h1[b] = feat_b @ W1  (HMMA split-bf16)
    {
        dim3 grid(M_PAD / 128);
        wmma_gemm_kernel<NHID, NFEAT><<<grid, 256>>>(
            x, w1h, w1l, h1 + 0 * (size_t)M_PAD * NHID, N_NODES);
        wmma_gemm_kernel<NHID, NFEAT><<<grid, 256>>>(
            dr1, w1h, w1l, h1 + 1 * (size_t)M_PAD * NHID, N_NODES);
        wmma_gemm_kernel<NHID, NFEAT><<<grid, 256>>>(
            dr2, w1h, w1l, h1 + 2 * (size_t)M_PAD * NHID, N_NODES);
    }

    // 2) SpMM1 + bias + relu
    {
        dim3 grid(N_NODES, 3);
        spmm1_bias_relu_kernel<<<grid, 32>>>(
            (const float4*)h1, esrc, ew, (const float4*)b1, (float4*)agg1);
    }

    // 3) GEMM2: h2 = agg1 @ W2  (all 3 branches as one M = 3*M_PAD GEMM)
    {
        dim3 grid(3 * M_PAD / 128);
        wmma_gemm_kernel<NCLASS, NHID><<<grid, 256>>>(
            agg1, w2h, w2l, h2, 3 * M_PAD);
    }

    // 4) SpMM2 + bias + log_softmax -> o1,o2,o3 straight to d_out
    {
        dim3 grid(N_NODES, 3);
        spmm2_lsm_kernel<<<grid, 32>>>(
            (const float4*)h2, esrc, ew, (const float4*)b2, out);
    }

    // 5) final = mean(o1,o2,o3)
    {
        const size_t total = (size_t)N_NODES * NCLASS;
        mean3_kernel<<<(unsigned)((total / 4 + 255) / 256), 256>>>(
            (const float4*)out, (float4*)(out + 3 * total));
    }
}

// round 10
// speedup vs baseline: 1.4938x; 1.1744x over previous
#include <cuda_runtime.h>
#include <cuda_bf16.h>
#include <mma.h>
#include <math.h>
#include <stdint.h>

using namespace nvcuda;

#define N_NODES 100000
#define N_EDGES 1600000
#define NFEAT 256
#define NHID 128
#define NCLASS 64
#define M_PAD 100096          // 782 * 128, padded row count per branch

// ---------------- scratch (device globals; no allocation) ----------------
// Pad rows [N_NODES, M_PAD) of g_agg1 are never written by any kernel (zero-init
// globals persist), so GEMM2's unguarded reads of them are deterministic zeros.
__device__ float g_h1[3u * M_PAD * NHID];
__device__ float g_agg1[3u * M_PAD * NHID];
__device__ float g_h2[3u * M_PAD * NCLASS];
__device__ int g_rowptr[N_NODES + 1];
__device__ __nv_bfloat16 g_W1_hi[NFEAT * NHID];
__device__ __nv_bfloat16 g_W1_lo[NFEAT * NHID];
__device__ __nv_bfloat16 g_W2_hi[NHID * NCLASS];
__device__ __nv_bfloat16 g_W2_lo[NHID * NCLASS];

__device__ __forceinline__ void split2(float v, __nv_bfloat16& h, __nv_bfloat16& l) {
    h = __float2bfloat16(v);
    l = __float2bfloat16(v - __bfloat162float(h));
}

// ---------------- row_ptr from sorted edge_dst ----------------
__global__ void build_rowptr_kernel(const int* __restrict__ dst) {
    int v = blockIdx.x * blockDim.x + threadIdx.x;
    if (v > N_NODES) return;
    int lo = 0, hi = N_EDGES;
    while (lo < hi) {
        int mid = (lo + hi) >> 1;
        if (dst[mid] < v) lo = mid + 1; else hi = mid;
    }
    g_rowptr[v] = lo;
}

// ---------------- W bf16 split ----------------
__global__ void prep_w_kernel(const float* __restrict__ W1, const float* __restrict__ W2) {
    int i = blockIdx.x * blockDim.x + threadIdx.x;
    if (i < NFEAT * NHID) {
        __nv_bfloat16 h, l;
        split2(W1[i], h, l);
        g_W1_hi[i] = h;
        g_W1_lo[i] = l;
    }
    if (i < NHID * NCLASS) {
        __nv_bfloat16 h, l;
        split2(W2[i], h, l);
        g_W2_hi[i] = h;
        g_W2_lo[i] = l;
    }
}

// ================= double-buffered split-bf16 GEMM (HMMA) =================
// C[M, N_DIM] = A[M, K_DIM] @ B[K_DIM, N_DIM];  acc += Ahi@Bhi + Ahi@Blo + Alo@Bhi
// Block tile 128 x N_DIM, BK=32, 256 threads; 2-stage smem pipeline:
//   ldg(kc+1) -> compute(kc) -> sts(kc+1) -> sync
template <int N_DIM, int K_DIM>
__global__ __launch_bounds__(256)
void wmma_gemm_kernel(const float* __restrict__ A,
                      const __nv_bfloat16* __restrict__ Bhi,
                      const __nv_bfloat16* __restrict__ Blo,
                      float* __restrict__ C, int M_A) {
    constexpr int BM = 128, BK = 32;
    constexpr int NCHUNK = K_DIM / BK;
    constexpr int LDA = BK + 8;
    constexpr int LDB = N_DIM + 8;
    constexpr int NF = N_DIM / 32;
    constexpr int MF = 2;
    constexpr int A_SZ = BM * LDA * 2;              // bytes per A array
    constexpr int B_SZ = BK * LDB * 2;              // bytes per B array
    constexpr int STAGE = 2 * A_SZ + 2 * B_SZ;
    constexpr int BU4 = BK * N_DIM / 8;             // uint4 per B array
    constexpr int B_PER = (BU4 + 255) / 256;        // per-thread B uint4 (per array)

    extern __shared__ char smem[];

    const int tid = threadIdx.x;
    const int wid = tid >> 5;
    const int warp_m = wid & 3;
    const int warp_n = wid >> 2;
    const int row0 = blockIdx.x * BM;

    // prefetch registers
    float4 a_pre[4];
    uint4 bh_pre[B_PER], bl_pre[B_PER];

    auto ldg_tile = [&](int kc) {
        const int k0 = kc * BK;
#pragma unroll
        for (int i = 0; i < 4; ++i) {
            int j = tid + i * 256;
            int m = j >> 3;
            int c = (j & 7) * 4;
            int gm = row0 + m;
            a_pre[i] = make_float4(0.f, 0.f, 0.f, 0.f);
            if (gm < M_A)
                a_pre[i] = *reinterpret_cast<const float4*>(A + (size_t)gm * K_DIM + k0 + c);
        }
#pragma unroll
        for (int i = 0; i < B_PER; ++i) {
            int j = tid + i * 256;
            if (j < BU4) {
                int r = j / (N_DIM / 8);
                int c8 = j % (N_DIM / 8);
                bh_pre[i] = *reinterpret_cast<const uint4*>(
                    Bhi + (size_t)(kc * BK + r) * N_DIM + c8 * 8);
                bl_pre[i] = *reinterpret_cast<const uint4*>(
                    Blo + (size_t)(kc * BK + r) * N_DIM + c8 * 8);
            }
        }
    };

    auto sts_tile = [&](int st) {
        char* base = smem + st * STAGE;
        __nv_bfloat16* As_hi = reinterpret_cast<__nv_bfloat16*>(base);
        __nv_bfloat16* As_lo = reinterpret_cast<__nv_bfloat16*>(base + A_SZ);
        __nv_bfloat16* Bs_hi = reinterpret_cast<__nv_bfloat16*>(base + 2 * A_SZ);
        __nv_bfloat16* Bs_lo = reinterpret_cast<__nv_bfloat16*>(base + 2 * A_SZ + B_SZ);
#pragma unroll
        for (int i = 0; i < 4; ++i) {
            int j = tid + i * 256;
            int m = j >> 3;
            int c = (j & 7) * 4;
            __nv_bfloat16 h0, l0, h1, l1, h2, l2, h3, l3;
            split2(a_pre[i].x, h0, l0); split2(a_pre[i].y, h1, l1);
            split2(a_pre[i].z, h2, l2); split2(a_pre[i].w, h3, l3);
            uint32_t hh0 = (uint32_t)__bfloat16_as_ushort(h0) |
                           ((uint32_t)__bfloat16_as_ushort(h1) << 16);
            uint32_t hh1 = (uint32_t)__bfloat16_as_ushort(h2) |
                           ((uint32_t)__bfloat16_as_ushort(h3) << 16);
            uint32_t ll0 = (uint32_t)__bfloat16_as_ushort(l0) |
                           ((uint32_t)__bfloat16_as_ushort(l1) << 16);
            uint32_t ll1 = (uint32_t)__bfloat16_as_ushort(l2) |
                           ((uint32_t)__bfloat16_as_ushort(l3) << 16);
            *reinterpret_cast<uint2*>(&As_hi[m * LDA + c]) = make_uint2(hh0, hh1);
            *reinterpret_cast<uint2*>(&As_lo[m * LDA + c]) = make_uint2(ll0, ll1);
        }
#pragma unroll
        for (int i = 0; i < B_PER; ++i) {
            int j = tid + i * 256;
            if (j < BU4) {
                int r = j / (N_DIM / 8);
                int c8 = j % (N_DIM / 8);
                *reinterpret_cast<uint4*>(&Bs_hi[r * LDB + c8 * 8]) = bh_pre[i];
                *reinterpret_cast<uint4*>(&Bs_lo[r * LDB + c8 * 8]) = bl_pre[i];
            }
        }
    };

    wmma::fragment<wmma::accumulator, 16, 16, 16, float> acc[MF][NF];
#pragma unroll
    for (int i = 0; i < MF; ++i)
#pragma unroll
        for (int j = 0; j < NF; ++j) wmma::fill_fragment(acc[i][j], 0.f);

    // prologue: fill stage 0
    ldg_tile(0);
    sts_tile(0);
    __syncthreads();

    for (int kc = 0; kc < NCHUNK; ++kc) {
        if (kc + 1 < NCHUNK) ldg_tile(kc + 1);   // issue gmem loads early

        // compute from stage kc&1
        {
            char* base = smem + (kc & 1) * STAGE;
            __nv_bfloat16* As_hi = reinterpret_cast<__nv_bfloat16*>(base);
            __nv_bfloat16* As_lo = reinterpret_cast<__nv_bfloat16*>(base + A_SZ);
            __nv_bfloat16* Bs_hi = reinterpret_cast<__nv_bfloat16*>(base + 2 * A_SZ);
            __nv_bfloat16* Bs_lo = reinterpret_cast<__nv_bfloat16*>(base + 2 * A_SZ + B_SZ);
#pragma unroll
            for (int kk = 0; kk < 2; ++kk) {
                wmma::fragment<wmma::matrix_a, 16, 16, 16, __nv_bfloat16, wmma::row_major> ah[MF], al[MF];
                wmma::fragment<wmma::matrix_b, 16, 16, 16, __nv_bfloat16, wmma::row_major> bh[NF], bl[NF];
#pragma unroll
                for (int i = 0; i < MF; ++i) {
                    const int r = (warp_m * 32 + i * 16) * LDA + kk * 16;
                    wmma::load_matrix_sync(ah[i], &As_hi[r], LDA);
                    wmma::load_matrix_sync(al[i], &As_lo[r], LDA);
                }
#pragma unroll
                for (int j = 0; j < NF; ++j) {
                    const int cidx = kk * 16 * LDB + warp_n * (N_DIM / 2) + j * 16;
                    wmma::load_matrix_sync(bh[j], &Bs_hi[cidx], LDB);
                    wmma::load_matrix_sync(bl[j], &Bs_lo[cidx], LDB);
                }
#pragma unroll
                for (int i = 0; i < MF; ++i)
#pragma unroll
                    for (int j = 0; j < NF; ++j) {
                        wmma::mma_sync(acc[i][j], ah[i], bh[j], acc[i][j]);
                        wmma::mma_sync(acc[i][j], ah[i], bl[j], acc[i][j]);
                        wmma::mma_sync(acc[i][j], al[i], bh[j], acc[i][j]);
                    }
            }
        }

        if (kc + 1 < NCHUNK) sts_tile((kc + 1) & 1);
        __syncthreads();
    }

    // epilogue (C rows padded to multiple of 128 -> unguarded)
#pragma unroll
    for (int i = 0; i < MF; ++i) {
        int gm = row0 + warp_m * 32 + i * 16;
#pragma unroll
        for (int j = 0; j < NF; ++j) {
            wmma::store_matrix_sync(C + (size_t)gm * N_DIM + warp_n * (N_DIM / 2) + j * 16,
                                    acc[i][j], N_DIM, wmma::mem_row_major);
        }
    }
}

// ---------------- SpMM layer 1: agg = relu(segsum(w * h1[src]) + b1) ----------------
// 256 threads = 8 warps; warp w handles pair p = blockIdx.x*8 + w over [0, 3*N_NODES)
// pair order branch-major -> one branch's h1 (51MB) stays L2-resident.
__global__ __launch_bounds__(256)
void spmm1_bias_relu_kernel(const float4* __restrict__ src_h,
                            const int* __restrict__ esrc,
                            const float* __restrict__ ew,
                            const float4* __restrict__ b1,
                            float4* __restrict__ outp) {
    const int p = blockIdx.x * 8 + (threadIdx.x >> 5);   // 37500 blocks * 8 = 300000 exact
    const int d = threadIdx.x & 31;
    const int b = p / N_NODES;
    const int v = p - b * N_NODES;
    const float4* Hb = src_h + (size_t)b * M_PAD * (NHID / 4);
    const int e0 = g_rowptr[v];
    const int e1 = g_rowptr[v + 1];
    float4 acc = make_float4(0.f, 0.f, 0.f, 0.f);
    int e = e0;
    for (; e + 2 <= e1; e += 2) {
        int s0 = __ldg(&esrc[e]);
        int s1 = __ldg(&esrc[e + 1]);
        float w0 = __ldg(&ew[e]);
        float w1 = __ldg(&ew[e + 1]);
        float4 h0 = __ldg(&Hb[(size_t)s0 * (NHID / 4) + d]);
        float4 h1v = __ldg(&Hb[(size_t)s1 * (NHID / 4) + d]);
        acc.x += w0 * h0.x; acc.y += w0 * h0.y; acc.z += w0 * h0.z; acc.w += w0 * h0.w;
        acc.x += w1 * h1v.x; acc.y += w1 * h1v.y; acc.z += w1 * h1v.z; acc.w += w1 * h1v.w;
    }
    if (e < e1) {
        int s0 = __ldg(&esrc[e]);
        float w0 = __ldg(&ew[e]);
        float4 h0 = __ldg(&Hb[(size_t)s0 * (NHID / 4) + d]);
        acc.x += w0 * h0.x; acc.y += w0 * h0.y; acc.z += w0 * h0.z; acc.w += w0 * h0.w;
    }
    float4 bb = __ldg(&b1[d]);
    float4 r;
    r.x = fmaxf(acc.x + bb.x, 0.f);
    r.y = fmaxf(acc.y + bb.y, 0.f);
    r.z = fmaxf(acc.z + bb.z, 0.f);
    r.w = fmaxf(acc.w + bb.w, 0.f);
    outp[((size_t)b * M_PAD + v) * (NHID / 4) + d] = r;
}

// ---------------- SpMM layer 2 + bias + log_softmax ----------------
// 256 threads = 8 warps; each warp handles 2 pairs (16 lanes each). All lanes active.
// 16-lane reductions via width-16 shuffles.
__global__ __launch_bounds__(256)
void spmm2_lsm_kernel(const float4* __restrict__ src_h,
                      const int* __restrict__ esrc,
                      const float* __restrict__ ew,
                      const float4* __restrict__ b2,
                      float* __restrict__ out) {
    const int lane = threadIdx.x & 31;
    const int half = lane >> 4;          // 0 or 1
    const int l16 = lane & 15;           // lane within 16-group
    const int p = blockIdx.x * 16 + (threadIdx.x >> 5) * 2 + half;  // 18750*16 = 300000 exact
    const int b = p / N_NODES;
    const int v = p - b * N_NODES;
    const float4* Hb = src_h + (size_t)b * M_PAD * (NCLASS / 4);
    const int e0 = g_rowptr[v];
    const int e1 = g_rowptr[v + 1];
    float4 acc = make_float4(0.f, 0.f, 0.f, 0.f);
    int e = e0;
    for (; e + 2 <= e1; e += 2) {
        int s0 = __ldg(&esrc[e]);
        int s1 = __ldg(&esrc[e + 1]);
        float w0 = __ldg(&ew[e]);
        float w1 = __ldg(&ew[e + 1]);
        float4 h0 = __ldg(&Hb[(size_t)s0 * (NCLASS / 4) + l16]);
        float4 h1v = __ldg(&Hb[(size_t)s1 * (NCLASS / 4) + l16]);
        acc.x += w0 * h0.x; acc.y += w0 * h0.y; acc.z += w0 * h0.z; acc.w += w0 * h0.w;
        acc.x += w1 * h1v.x; acc.y += w1 * h1v.y; acc.z += w1 * h1v.z; acc.w += w1 * h1v.w;
    }
    if (e < e1) {
        int s0 = __ldg(&esrc[e]);
        float w0 = __ldg(&ew[e]);
        float4 h0 = __ldg(&Hb[(size_t)s0 * (NCLASS / 4) + l16]);
        acc.x += w0 * h0.x; acc.y += w0 * h0.y; acc.z += w0 * h0.z; acc.w += w0 * h0.w;
    }
    float4 bb = __ldg(&b2[l16]);
    acc.x += bb.x; acc.y += bb.y; acc.z += bb.z; acc.w += bb.w;

    // log-softmax over the 64 values spread across this 16-lane group
    float m = fmaxf(fmaxf(acc.x, acc.y), fmaxf(acc.z, acc.w));
#pragma unroll
    for (int o = 8; o; o >>= 1) m = fmaxf(m, __shfl_xor_sync(0xffffffffu, m, o, 16));

    float s = expf(acc.x - m) + expf(acc.y - m) + expf(acc.z - m) + expf(acc.w - m);
#pragma unroll
    for (int o = 8; o; o >>= 1) s += __shfl_xor_sync(0xffffffffu, s, o, 16);

    float lse = m + logf(s);
    float4 r;
    r.x = acc.x - lse; r.y = acc.y - lse; r.z = acc.z - lse; r.w = acc.w - lse;
    float4* ob = reinterpret_cast<float4*>(
        out + (size_t)b * N_NODES * NCLASS + (size_t)v * NCLASS);
    ob[l16] = r;
}

// ---------------- final mean of 3 branches ----------------
__global__ void mean3_kernel(const float4* __restrict__ out_base, float4* __restrict__ fin) {
    size_t i = (size_t)blockIdx.x * blockDim.x + threadIdx.x;
    const size_t total = (size_t)N_NODES * NCLASS / 4;
    if (i >= total) return;
    float4 a = out_base[i];
    float4 bb = out_base[total + i];
    float4 c = out_base[2 * total + i];
    float4 r;
    r.x = (a.x + bb.x + c.x) * (1.0f / 3.0f);
    r.y = (a.y + bb.y + c.y) * (1.0f / 3.0f);
    r.z = (a.z + bb.z + c.z) * (1.0f / 3.0f);
    r.w = (a.w + bb.w + c.w) * (1.0f / 3.0f);
    fin[i] = r;
}

// ---------------- launch ----------------
extern "C" void kernel_launch(void* const* d_in, const int* in_sizes, int n_in,
                              void* d_out, int out_size) {
    const float* x   = (const float*)d_in[0];
    const float* dr1 = (const float*)d_in[1];
    const float* dr2 = (const float*)d_in[2];
    const int*   esrc = (const int*)d_in[3];
    const int*   edst = (const int*)d_in[4];
    const float* ew  = (const float*)d_in[5];
    const float* W1  = (const float*)d_in[6];
    const float* b1  = (const float*)d_in[7];
    const float* W2  = (const float*)d_in[8];
    const float* b2  = (const float*)d_in[9];
    float* out = (float*)d_out;

    float *h1, *agg1, *h2;
    cudaGetSymbolAddress((void**)&h1, g_h1);
    cudaGetSymbolAddress((void**)&agg1, g_agg1);
    cudaGetSymbolAddress((void**)&h2, g_h2);
    __nv_bfloat16 *w1h, *w1l, *w2h, *w2l;
    cudaGetSymbolAddress((void**)&w1h, g_W1_hi);
    cudaGetSymbolAddress((void**)&w1l, g_W1_lo);
    cudaGetSymbolAddress((void**)&w2h, g_W2_hi);
    cudaGetSymbolAddress((void**)&w2l, g_W2_lo);

    // dynamic smem sizes (2 stages) — set unconditionally every call (idempotent;
    // static guards are forbidden by the harness rules)
    constexpr int LDA = 40;
    constexpr int SMEM1 = 2 * (2 * 128 * LDA * 2 + 2 * 32 * (NHID + 8) * 2);   // 75776
    constexpr int SMEM2 = 2 * (2 * 128 * LDA * 2 + 2 * 32 * (NCLASS + 8) * 2); // 59392
    cudaFuncSetAttribute(wmma_gemm_kernel<NHID, NFEAT>,
                         cudaFuncAttributeMaxDynamicSharedMemorySize, SMEM1);
    cudaFuncSetAttribute(wmma_gemm_kernel<NCLASS, NHID>,
                         cudaFuncAttributeMaxDynamicSharedMemorySize, SMEM2);

    // 0) prep: row pointers + W split
    build_rowptr_kernel<<<(N_NODES + 1 + 255) / 256, 256>>>(edst);
    prep_w_kernel<<<(NFEAT * NHID + 255) / 256, 256>>>(W1, W2);

    // 1) GEMM1 per branch: h1[b] = feat_b @ W1  (HMMA split-bf16, double-buffered)
    {
        dim3 grid(M_PAD / 128);
        wmma_gemm_kernel<NHID, NFEAT><<<grid, 256, SMEM1>>>(
            x, w1h, w1l, h1 + 0 * (size_t)M_PAD * NHID, N_NODES);
        wmma_gemm_kernel<NHID, NFEAT><<<grid, 256, SMEM1>>>(
            dr1, w1h, w1l, h1 + 1 * (size_t)M_PAD * NHID, N_NODES);
        wmma_gemm_kernel<NHID, NFEAT><<<grid, 256, SMEM1>>>(
            dr2, w1h, w1l, h1 + 2 * (size_t)M_PAD * NHID, N_NODES);
    }

    // 2) SpMM1 + bias + relu (8 pairs per 256-thread block, branch-major)
    spmm1_bias_relu_kernel<<<3 * N_NODES / 8, 256>>>(
        (const float4*)h1, esrc, ew, (const float4*)b1, (float4*)agg1);

    // 3) GEMM2: h2 = agg1 @ W2  (all 3 branches, M = 3*M_PAD)
    {
        dim3 grid(3 * M_PAD / 128);
        wmma_gemm_kernel<NCLASS, NHID><<<grid, 256, SMEM2>>>(
            agg1, w2h, w2l, h2, 3 * M_PAD);
    }

    // 4) SpMM2 + bias + log_softmax (16 pairs per 256-thread block)
    spmm2_lsm_kernel<<<3 * N_NODES / 16, 256>>>(
        (const float4*)h2, esrc, ew, (const float4*)b2, out);

    // 5) final = mean(o1,o2,o3)
    {
        const size_t total = (size_t)N_NODES * NCLASS;
        mean3_kernel<<<(unsigned)((total / 4 + 255) / 256), 256>>>(
            (const float4*)out, (float4*)(out + 3 * total));
    }
}

// round 12
// speedup vs baseline: 1.8370x; 1.2298x over previous
#include <cuda_runtime.h>
#include <cuda_bf16.h>
#include <mma.h>
#include <math.h>
#include <stdint.h>

using namespace nvcuda;

#define N_NODES 100000
#define N_EDGES 1600000
#define NFEAT 256
#define NHID 128
#define NCLASS 64
#define M_PAD 100096          // 782 * 128, padded row count per branch

// ---------------- scratch (device globals; no allocation) ----------------
// Pad rows [N_NODES, M_PAD) of g_agg1 are never written by any kernel (zero-init
// globals persist), so GEMM2's unguarded reads of them are deterministic zeros.
__device__ float g_h1[3u * M_PAD * NHID];
__device__ float g_agg1[3u * M_PAD * NHID];
__device__ float g_h2[3u * M_PAD * NCLASS];
__device__ int g_rowptr[N_NODES + 1];
__device__ __nv_bfloat16 g_W1_hi[NFEAT * NHID];
__device__ __nv_bfloat16 g_W1_lo[NFEAT * NHID];
__device__ __nv_bfloat16 g_W2_hi[NHID * NCLASS];
__device__ __nv_bfloat16 g_W2_lo[NHID * NCLASS];

__device__ __forceinline__ void split2(float v, __nv_bfloat16& h, __nv_bfloat16& l) {
    h = __float2bfloat16(v);
    l = __float2bfloat16(v - __bfloat162float(h));
}

__device__ __forceinline__ uint32_t smem_u32(const void* p) {
    return (uint32_t)__cvta_generic_to_shared(p);
}
#define CP_ASYNC16(dst_u32, gptr) \
    asm volatile("cp.async.cg.shared.global [%0], [%1], 16;" :: "r"(dst_u32), "l"(gptr))
#define CP_COMMIT()  asm volatile("cp.async.commit_group;" ::: "memory")
#define CP_WAIT0()   asm volatile("cp.async.wait_group 0;" ::: "memory")

// ---------------- row_ptr from sorted edge_dst ----------------
__global__ void build_rowptr_kernel(const int* __restrict__ dst) {
    int v = blockIdx.x * blockDim.x + threadIdx.x;
    if (v > N_NODES) return;
    int lo = 0, hi = N_EDGES;
    while (lo < hi) {
        int mid = (lo + hi) >> 1;
        if (dst[mid] < v) lo = mid + 1; else hi = mid;
    }
    g_rowptr[v] = lo;
}

// ---------------- W bf16 split ----------------
__global__ void prep_w_kernel(const float* __restrict__ W1, const float* __restrict__ W2) {
    int i = blockIdx.x * blockDim.x + threadIdx.x;
    if (i < NFEAT * NHID) {
        __nv_bfloat16 h, l;
        split2(W1[i], h, l);
        g_W1_hi[i] = h;
        g_W1_lo[i] = l;
    }
    if (i < NHID * NCLASS) {
        __nv_bfloat16 h, l;
        split2(W2[i], h, l);
        g_W2_hi[i] = h;
        g_W2_lo[i] = l;
    }
}

// ================= split-bf16 GEMM, 2 CTAs/SM, cp.async B =================
// C[M, N_DIM] = A[M, K_DIM] @ B[K_DIM, N_DIM];  acc += Ahi@Bhi + Ahi@Blo + Alo@Bhi
// grid.y selects branch: A = {A0,A1,A2}[y], C += y * M_PAD * N_DIM.
// 2-stage pipeline: A via reg-prefetch+convert, B via cp.async.
template <int N_DIM, int K_DIM>
__global__ __launch_bounds__(256, 2)
void wmma_gemm_kernel(const float* __restrict__ A0,
                      const float* __restrict__ A1,
                      const float* __restrict__ A2,
                      const __nv_bfloat16* __restrict__ Bhi,
                      const __nv_bfloat16* __restrict__ Blo,
                      float* __restrict__ C, int M_A) {
    constexpr int BM = 128, BK = 32;
    constexpr int NCHUNK = K_DIM / BK;
    constexpr int LDA = BK + 8;
    constexpr int LDB = N_DIM + 8;
    constexpr int NF = N_DIM / 32;
    constexpr int MF = 2;
    constexpr int A_SZ = BM * LDA * 2;              // bytes per A array
    constexpr int B_SZ = BK * LDB * 2;              // bytes per B array
    constexpr int STAGE = 2 * A_SZ + 2 * B_SZ;
    constexpr int B_CH = BK * N_DIM / 8;            // 16B chunks per B array
    constexpr int B_PER = (B_CH + 255) / 256;

    extern __shared__ char smem[];

    const int tid = threadIdx.x;
    const int wid = tid >> 5;
    const int warp_m = wid & 3;
    const int warp_n = wid >> 2;
    const int row0 = blockIdx.x * BM;
    const float* __restrict__ A = (blockIdx.y == 0) ? A0 : (blockIdx.y == 1) ? A1 : A2;
    C += (size_t)blockIdx.y * M_PAD * N_DIM;

    float4 a_pre[4];

    auto ldg_A = [&](int kc) {
        const int k0 = kc * BK;
#pragma unroll
        for (int i = 0; i < 4; ++i) {
            int j = tid + i * 256;
            int m = j >> 3;
            int c = (j & 7) * 4;
            int gm = row0 + m;
            a_pre[i] = make_float4(0.f, 0.f, 0.f, 0.f);
            if (gm < M_A)
                a_pre[i] = *reinterpret_cast<const float4*>(A + (size_t)gm * K_DIM + k0 + c);
        }
    };

    auto cp_B = [&](int kc, int st) {
        char* base = smem + st * STAGE;
        uint32_t bhi_s = smem_u32(base + 2 * A_SZ);
        uint32_t blo_s = smem_u32(base + 2 * A_SZ + B_SZ);
        const int k0 = kc * BK;
#pragma unroll
        for (int i = 0; i < B_PER; ++i) {
            int j = tid + i * 256;
            if (j < B_CH) {
                int r = j / (N_DIM / 8);
                int c8 = j % (N_DIM / 8);
                uint32_t so = (uint32_t)(r * LDB + c8 * 8) * 2;
                const __nv_bfloat16* gh = Bhi + (size_t)(k0 + r) * N_DIM + c8 * 8;
                const __nv_bfloat16* gl = Blo + (size_t)(k0 + r) * N_DIM + c8 * 8;
                CP_ASYNC16(bhi_s + so, gh);
                CP_ASYNC16(blo_s + so, gl);
            }
        }
        CP_COMMIT();
    };

    auto sts_A = [&](int st) {
        char* base = smem + st * STAGE;
        __nv_bfloat16* As_hi = reinterpret_cast<__nv_bfloat16*>(base);
        __nv_bfloat16* As_lo = reinterpret_cast<__nv_bfloat16*>(base + A_SZ);
#pragma unroll
        for (int i = 0; i < 4; ++i) {
            int j = tid + i * 256;
            int m = j >> 3;
            int c = (j & 7) * 4;
            __nv_bfloat16 h0, l0, h1, l1, h2, l2, h3, l3;
            split2(a_pre[i].x, h0, l0); split2(a_pre[i].y, h1, l1);
            split2(a_pre[i].z, h2, l2); split2(a_pre[i].w, h3, l3);
            uint32_t hh0 = (uint32_t)__bfloat16_as_ushort(h0) |
                           ((uint32_t)__bfloat16_as_ushort(h1) << 16);
            uint32_t hh1 = (uint32_t)__bfloat16_as_ushort(h2) |
                           ((uint32_t)__bfloat16_as_ushort(h3) << 16);
            uint32_t ll0 = (uint32_t)__bfloat16_as_ushort(l0) |
                           ((uint32_t)__bfloat16_as_ushort(l1) << 16);
            uint32_t ll1 = (uint32_t)__bfloat16_as_ushort(l2) |
                           ((uint32_t)__bfloat16_as_ushort(l3) << 16);
            *reinterpret_cast<uint2*>(&As_hi[m * LDA + c]) = make_uint2(hh0, hh1);
            *reinterpret_cast<uint2*>(&As_lo[m * LDA + c]) = make_uint2(ll0, ll1);
        }
    };

    wmma::fragment<wmma::accumulator, 16, 16, 16, float> acc[MF][NF];
#pragma unroll
    for (int i = 0; i < MF; ++i)
#pragma unroll
        for (int j = 0; j < NF; ++j) wmma::fill_fragment(acc[i][j], 0.f);

    // prologue: stage 0
    ldg_A(0);
    cp_B(0, 0);
    sts_A(0);
    CP_WAIT0();
    __syncthreads();

    for (int kc = 0; kc < NCHUNK; ++kc) {
        if (kc + 1 < NCHUNK) {
            ldg_A(kc + 1);
            cp_B(kc + 1, (kc + 1) & 1);
        }

        // compute from stage kc&1
        {
            char* base = smem + (kc & 1) * STAGE;
            __nv_bfloat16* As_hi = reinterpret_cast<__nv_bfloat16*>(base);
            __nv_bfloat16* As_lo = reinterpret_cast<__nv_bfloat16*>(base + A_SZ);
            __nv_bfloat16* Bs_hi = reinterpret_cast<__nv_bfloat16*>(base + 2 * A_SZ);
            __nv_bfloat16* Bs_lo = reinterpret_cast<__nv_bfloat16*>(base + 2 * A_SZ + B_SZ);
#pragma unroll
            for (int kk = 0; kk < 2; ++kk) {
                wmma::fragment<wmma::matrix_a, 16, 16, 16, __nv_bfloat16, wmma::row_major> ah[MF], al[MF];
#pragma unroll
                for (int i = 0; i < MF; ++i) {
                    const int r = (warp_m * 32 + i * 16) * LDA + kk * 16;
                    wmma::load_matrix_sync(ah[i], &As_hi[r], LDA);
                    wmma::load_matrix_sync(al[i], &As_lo[r], LDA);
                }
#pragma unroll
                for (int j = 0; j < NF; ++j) {
                    wmma::fragment<wmma::matrix_b, 16, 16, 16, __nv_bfloat16, wmma::row_major> bh, bl;
                    const int cidx = kk * 16 * LDB + warp_n * (N_DIM / 2) + j * 16;
                    wmma::load_matrix_sync(bh, &Bs_hi[cidx], LDB);
                    wmma::load_matrix_sync(bl, &Bs_lo[cidx], LDB);
#pragma unroll
                    for (int i = 0; i < MF; ++i) {
                        wmma::mma_sync(acc[i][j], ah[i], bh, acc[i][j]);
                        wmma::mma_sync(acc[i][j], ah[i], bl, acc[i][j]);
                        wmma::mma_sync(acc[i][j], al[i], bh, acc[i][j]);
                    }
                }
            }
        }

        if (kc + 1 < NCHUNK) {
            sts_A((kc + 1) & 1);
            CP_WAIT0();          // B(kc+1) landed
        }
        __syncthreads();         // publish stage kc+1; retire reads of stage kc
    }

    // epilogue (C rows padded to multiple of 128 -> unguarded)
#pragma unroll
    for (int i = 0; i < MF; ++i) {
        int gm = row0 + warp_m * 32 + i * 16;
#pragma unroll
        for (int j = 0; j < NF; ++j) {
            wmma::store_matrix_sync(C + (size_t)gm * N_DIM + warp_n * (N_DIM / 2) + j * 16,
                                    acc[i][j], N_DIM, wmma::mem_row_major);
        }
    }
}

// ---------------- SpMM layer 1: agg = relu(segsum(w * h1[src]) + b1) ----------------
// 256 threads = 8 warps; warp w handles pair p = blockIdx.x*8 + w over [0, 3*N_NODES)
__global__ __launch_bounds__(256)
void spmm1_bias_relu_kernel(const float4* __restrict__ src_h,
                            const int* __restrict__ esrc,
                            const float* __restrict__ ew,
                            const float4* __restrict__ b1,
                            float4* __restrict__ outp) {
    const int p = blockIdx.x * 8 + (threadIdx.x >> 5);   // 37500 blocks * 8 = 300000 exact
    const int d = threadIdx.x & 31;
    const int b = p / N_NODES;
    const int v = p - b * N_NODES;
    const float4* Hb = src_h + (size_t)b * M_PAD * (NHID / 4);
    const int e0 = g_rowptr[v];
    const int e1 = g_rowptr[v + 1];
    float4 acc = make_float4(0.f, 0.f, 0.f, 0.f);
    int e = e0;
    for (; e + 2 <= e1; e += 2) {
        int s0 = __ldg(&esrc[e]);
        int s1 = __ldg(&esrc[e + 1]);
        float w0 = __ldg(&ew[e]);
        float w1 = __ldg(&ew[e + 1]);
        float4 h0 = __ldg(&Hb[(size_t)s0 * (NHID / 4) + d]);
        float4 h1v = __ldg(&Hb[(size_t)s1 * (NHID / 4) + d]);
        acc.x += w0 * h0.x; acc.y += w0 * h0.y; acc.z += w0 * h0.z; acc.w += w0 * h0.w;
        acc.x += w1 * h1v.x; acc.y += w1 * h1v.y; acc.z += w1 * h1v.z; acc.w += w1 * h1v.w;
    }
    if (e < e1) {
        int s0 = __ldg(&esrc[e]);
        float w0 = __ldg(&ew[e]);
        float4 h0 = __ldg(&Hb[(size_t)s0 * (NHID / 4) + d]);
        acc.x += w0 * h0.x; acc.y += w0 * h0.y; acc.z += w0 * h0.z; acc.w += w0 * h0.w;
    }
    float4 bb = __ldg(&b1[d]);
    float4 r;
    r.x = fmaxf(acc.x + bb.x, 0.f);
    r.y = fmaxf(acc.y + bb.y, 0.f);
    r.z = fmaxf(acc.z + bb.z, 0.f);
    r.w = fmaxf(acc.w + bb.w, 0.f);
    outp[((size_t)b * M_PAD + v) * (NHID / 4) + d] = r;
}

// ---------------- SpMM layer 2 + bias + log_softmax ----------------
// 256 threads = 8 warps; each warp handles 2 pairs (16 lanes each).
__global__ __launch_bounds__(256)
void spmm2_lsm_kernel(const float4* __restrict__ src_h,
                      const int* __restrict__ esrc,
                      const float* __restrict__ ew,
                      const float4* __restrict__ b2,
                      float* __restrict__ out) {
    const int lane = threadIdx.x & 31;
    const int half = lane >> 4;
    const int l16 = lane & 15;
    const int p = blockIdx.x * 16 + (threadIdx.x >> 5) * 2 + half;  // 18750*16 = 300000 exact
    const int b = p / N_NODES;
    const int v = p - b * N_NODES;
    const float4* Hb = src_h + (size_t)b * M_PAD * (NCLASS / 4);
    const int e0 = g_rowptr[v];
    const int e1 = g_rowptr[v + 1];
    float4 acc = make_float4(0.f, 0.f, 0.f, 0.f);
    int e = e0;
    for (; e + 2 <= e1; e += 2) {
        int s0 = __ldg(&esrc[e]);
        int s1 = __ldg(&esrc[e + 1]);
        float w0 = __ldg(&ew[e]);
        float w1 = __ldg(&ew[e + 1]);
        float4 h0 = __ldg(&Hb[(size_t)s0 * (NCLASS / 4) + l16]);
        float4 h1v = __ldg(&Hb[(size_t)s1 * (NCLASS / 4) + l16]);
        acc.x += w0 * h0.x; acc.y += w0 * h0.y; acc.z += w0 * h0.z; acc.w += w0 * h0.w;
        acc.x += w1 * h1v.x; acc.y += w1 * h1v.y; acc.z += w1 * h1v.z; acc.w += w1 * h1v.w;
    }
    if (e < e1) {
        int s0 = __ldg(&esrc[e]);
        float w0 = __ldg(&ew[e]);
        float4 h0 = __ldg(&Hb[(size_t)s0 * (NCLASS / 4) + l16]);
        acc.x += w0 * h0.x; acc.y += w0 * h0.y; acc.z += w0 * h0.z; acc.w += w0 * h0.w;
    }
    float4 bb = __ldg(&b2[l16]);
    acc.x += bb.x; acc.y += bb.y; acc.z += bb.z; acc.w += bb.w;

    float m = fmaxf(fmaxf(acc.x, acc.y), fmaxf(acc.z, acc.w));
#pragma unroll
    for (int o = 8; o; o >>= 1) m = fmaxf(m, __shfl_xor_sync(0xffffffffu, m, o, 16));

    float s = expf(acc.x - m) + expf(acc.y - m) + expf(acc.z - m) + expf(acc.w - m);
#pragma unroll
    for (int o = 8; o; o >>= 1) s += __shfl_xor_sync(0xffffffffu, s, o, 16);

    float lse = m + logf(s);
    float4 r;
    r.x = acc.x - lse; r.y = acc.y - lse; r.z = acc.z - lse; r.w = acc.w - lse;
    float4* ob = reinterpret_cast<float4*>(
        out + (size_t)b * N_NODES * NCLASS + (size_t)v * NCLASS);
    ob[l16] = r;
}

// ---------------- final mean of 3 branches ----------------
__global__ void mean3_kernel(const float4* __restrict__ out_base, float4* __restrict__ fin) {
    size_t i = (size_t)blockIdx.x * blockDim.x + threadIdx.x;
    const size_t total = (size_t)N_NODES * NCLASS / 4;
    if (i >= total) return;
    float4 a = out_base[i];
    float4 bb = out_base[total + i];
    float4 c = out_base[2 * total + i];
    float4 r;
    r.x = (a.x + bb.x + c.x) * (1.0f / 3.0f);
    r.y = (a.y + bb.y + c.y) * (1.0f / 3.0f);
    r.z = (a.z + bb.z + c.z) * (1.0f / 3.0f);
    r.w = (a.w + bb.w + c.w) * (1.0f / 3.0f);
    fin[i] = r;
}

// ---------------- launch ----------------
extern "C" void kernel_launch(void* const* d_in, const int* in_sizes, int n_in,
                              void* d_out, int out_size) {
    const float* x   = (const float*)d_in[0];
    const float* dr1 = (const float*)d_in[1];
    const float* dr2 = (const float*)d_in[2];
    const int*   esrc = (const int*)d_in[3];
    const int*   edst = (const int*)d_in[4];
    const float* ew  = (const float*)d_in[5];
    const float* W1  = (const float*)d_in[6];
    const float* b1  = (const float*)d_in[7];
    const float* W2  = (const float*)d_in[8];
    const float* b2  = (const float*)d_in[9];
    float* out = (float*)d_out;

    float *h1, *agg1, *h2;
    cudaGetSymbolAddress((void**)&h1, g_h1);
    cudaGetSymbolAddress((void**)&agg1, g_agg1);
    cudaGetSymbolAddress((void**)&h2, g_h2);
    __nv_bfloat16 *w1h, *w1l, *w2h, *w2l;
    cudaGetSymbolAddress((void**)&w1h, g_W1_hi);
    cudaGetSymbolAddress((void**)&w1l, g_W1_lo);
    cudaGetSymbolAddress((void**)&w2h, g_W2_hi);
    cudaGetSymbolAddress((void**)&w2l, g_W2_lo);

    // dynamic smem sizes (2 stages); set unconditionally (idempotent; no static guards)
    constexpr int LDA = 40;
    constexpr int SMEM1 = 2 * (2 * 128 * LDA * 2 + 2 * 32 * (NHID + 8) * 2);   // 75776
    constexpr int SMEM2 = 2 * (2 * 128 * LDA * 2 + 2 * 32 * (NCLASS + 8) * 2); // 59392
    cudaFuncSetAttribute(wmma_gemm_kernel<NHID, NFEAT>,
                         cudaFuncAttributeMaxDynamicSharedMemorySize, SMEM1);
    cudaFuncSetAttribute(wmma_gemm_kernel<NCLASS, NHID>,
                         cudaFuncAttributeMaxDynamicSharedMemorySize, SMEM2);

    // 0) prep: row pointers + W split
    build_rowptr_kernel<<<(N_NODES + 1 + 255) / 256, 256>>>(edst);
    prep_w_kernel<<<(NFEAT * NHID + 255) / 256, 256>>>(W1, W2);

    // 1) GEMM1 all 3 branches in ONE launch (grid.y = branch)
    {
        dim3 grid(M_PAD / 128, 3);
        wmma_gemm_kernel<NHID, NFEAT><<<grid, 256, SMEM1>>>(
            x, dr1, dr2, w1h, w1l, h1, N_NODES);
    }

    // 2) SpMM1 + bias + relu
    spmm1_bias_relu_kernel<<<3 * N_NODES / 8, 256>>>(
        (const float4*)h1, esrc, ew, (const float4*)b1, (float4*)agg1);

    // 3) GEMM2: h2 = agg1 @ W2 (all 3 branches as one M = 3*M_PAD, grid.y = 1)
    {
        dim3 grid(3 * M_PAD / 128, 1);
        wmma_gemm_kernel<NCLASS, NHID><<<grid, 256, SMEM2>>>(
            agg1, agg1, agg1, w2h, w2l, h2, 3 * M_PAD);
    }

    // 4) SpMM2 + bias + log_softmax -> o1,o2,o3 straight to d_out
    spmm2_lsm_kernel<<<3 * N_NODES / 16, 256>>>(
        (const float4*)h2, esrc, ew, (const float4*)b2, out);

    // 5) final = mean(o1,o2,o3)
    {
        const size_t total = (size_t)N_NODES * NCLASS;
        mean3_kernel<<<(unsigned)((total / 4 + 255) / 256), 256>>>(
            (const float4*)out, (float4*)(out + 3 * total));
    }
}